// round 17
// baseline (speedup 1.0000x reference)
#include <cuda_runtime.h>
#include <cuda_fp16.h>
#include <stdint.h>
#include <math.h>

// Problem constants
#define D        256
#define NE       8192
#define T_TOTAL  32768
#define BETA     0.25f

// GEMM tiling (fp16 inputs, fp32 accum, K=256)
#define BM       128
#define BN       128
#define STG_KS   4
#define NIT      256           // 64 chunks * 4 stages
#define THREADS  256

#define SA_BYTES (8 * 16 * 32 * 16)    // 65536
#define SB_BYTES (4 * 8 * 32 * 16)     // 16384: [ksl][hpair][lane] uint4

#define ESCALE   16384.0f              // 2^14 emb prescale (exact)
#define DESCALE  0.0001220703125f      // 2^-13

#define NC       32                    // per-(token,owner) candidate capacity

// Scratch (device globals; no runtime allocation)
__device__ uint4  g_za[2048 * 512];                    // 16 MB: A frags
__device__ uint4  g_eb4[512 * 512];                    // 4 MB:  paired B frags
__device__ int2   g_cand[(size_t)T_TOTAL * 8 * NC];    // 64 MB: (m2 bits, e)
__device__ int    g_ccnt[T_TOTAL * 8];
__device__ float  g_rmax[T_TOTAL * 8];
__device__ float  g_z2[T_TOTAL];
__device__ float  g_az[T_TOTAL];
__device__ float  g_partial[4096];

// ---------------------------------------------------------------------------
__device__ __forceinline__ uint32_t smem_u32(const void* p) {
    uint32_t a;
    asm("{ .reg .u64 t; cvta.to.shared.u64 t, %1; cvt.u32.u64 %0, t; }" : "=r"(a) : "l"(p));
    return a;
}
__device__ __forceinline__ void cp_async16(uint32_t dst, const void* src) {
    asm volatile("cp.async.cg.shared.global [%0], [%1], 16;" :: "r"(dst), "l"(src));
}
__device__ __forceinline__ void cp_commit() {
    asm volatile("cp.async.commit_group;" ::: "memory");
}
__device__ __forceinline__ void cp_wait1() {
    asm volatile("cp.async.wait_group 1;" ::: "memory");
}
__device__ __forceinline__ void cp_wait0() {
    asm volatile("cp.async.wait_group 0;" ::: "memory");
}
__device__ __forceinline__ void mma_f16(float* c, const uint4 a, uint32_t b0, uint32_t b1) {
    asm volatile(
        "mma.sync.aligned.m16n8k16.row.col.f32.f16.f16.f32 "
        "{%0,%1,%2,%3}, {%4,%5,%6,%7}, {%8,%9}, {%0,%1,%2,%3};"
        : "+f"(c[0]), "+f"(c[1]), "+f"(c[2]), "+f"(c[3])
        : "r"(a.x), "r"(a.y), "r"(a.z), "r"(a.w), "r"(b0), "r"(b1));
}
__device__ __forceinline__ float ulp_of(float x) {
    return __uint_as_float(((__float_as_uint(x) >> 23) - 23) << 23);
}
__device__ __forceinline__ uint32_t pack_h2(float a, float b) {
    __half2 h = __floats2half2_rn(a, b);
    return *reinterpret_cast<uint32_t*>(&h);
}
// hard-bound margin (validated in rounds 10/12/14/16)
__device__ __forceinline__ float margin_of(float z2, float az) {
    float eps_a = 0.001953125f * 1.2207031e-4f * az + 8.2e-6f;
    return ulp_of(z2) + 2.0f * eps_a + 1.7e-5f;
}

// ---------------------------------------------------------------------------
// Prep A: z -> fp16 mma-A fragments. [g][ks][lane] uint4.
// ---------------------------------------------------------------------------
__global__ void vq_prep_z(const float* __restrict__ z) {
    int g = blockIdx.x;                 // 0..2047
    int tid = threadIdx.x;
    uint4* out = g_za + (size_t)g * 512;
#pragma unroll
    for (int it = 0; it < 2; it++) {
        int idx = tid + it * THREADS;
        int ks = idx >> 5, l = idx & 31;
        int gid = l >> 2, tig = l & 3;
        int kb = ks * 16 + 2 * tig;
        const float* r0 = z + (size_t)(g * 16 + gid) * D;
        const float* r1 = r0 + 8 * D;
        float2 p0 = *(const float2*)(r0 + kb);
        float2 p1 = *(const float2*)(r1 + kb);
        float2 p2 = *(const float2*)(r0 + kb + 8);
        float2 p3 = *(const float2*)(r1 + kb + 8);
        uint4 v;
        v.x = pack_h2(p0.x, p0.y);
        v.y = pack_h2(p1.x, p1.y);
        v.z = pack_h2(p2.x, p2.y);
        v.w = pack_h2(p3.x, p3.y);
        out[idx] = v;
    }
}

// ---------------------------------------------------------------------------
// Prep B: emb * 2^14 -> PAIRED fp16 mma-B fragments.
// g_eb4[hpair][ks][lane] = { frag(h=2*hpair), frag(h=2*hpair+1) }
//   .x/.y = b0/b1 for codes hpair*16 + gid,  .z/.w = for codes hpair*16+8+gid
// ---------------------------------------------------------------------------
__global__ void vq_prep_e(const float* __restrict__ emb) {
    int hp = blockIdx.x;                // 0..511
    int tid = threadIdx.x;
    uint4* out = g_eb4 + (size_t)hp * 512;
#pragma unroll
    for (int it = 0; it < 2; it++) {
        int idx = tid + it * THREADS;   // 0..511 = ks*32 + l
        int ks = idx >> 5, l = idx & 31;
        int gid = l >> 2, tig = l & 3;
        int kb = ks * 16 + 2 * tig;
        const float* r0 = emb + (size_t)(hp * 16 + gid) * D;
        const float* r1 = emb + (size_t)(hp * 16 + 8 + gid) * D;
        float2 p0 = *(const float2*)(r0 + kb);
        float2 p1 = *(const float2*)(r0 + kb + 8);
        float2 q0 = *(const float2*)(r1 + kb);
        float2 q1 = *(const float2*)(r1 + kb + 8);
        uint4 v;
        v.x = pack_h2(p0.x * ESCALE, p0.y * ESCALE);
        v.y = pack_h2(p1.x * ESCALE, p1.y * ESCALE);
        v.z = pack_h2(q0.x * ESCALE, q0.y * ESCALE);
        v.w = pack_h2(q1.x * ESCALE, q1.y * ESCALE);
        out[idx] = v;
    }
}

// ---------------------------------------------------------------------------
// Token norms: z2 = sum z^2, az = sum |z|. One warp per token.
// ---------------------------------------------------------------------------
__global__ void vq_norms(const float* __restrict__ z) {
    int t = (blockIdx.x * blockDim.x + threadIdx.x) >> 5;
    int lane = threadIdx.x & 31;
    if (t >= T_TOTAL) return;
    const float* row = z + (size_t)t * D;
    float s2 = 0.f, sa = 0.f;
#pragma unroll
    for (int i = 0; i < D / 32; i++) {
        float v = row[lane + 32 * i];
        s2 = fmaf(v, v, s2);
        sa += fabsf(v);
    }
#pragma unroll
    for (int o = 16; o; o >>= 1) {
        s2 += __shfl_xor_sync(0xffffffffu, s2, o);
        sa += __shfl_xor_sync(0xffffffffu, sa, o);
    }
    if (lane == 0) { g_z2[t] = s2; g_az[t] = sa; }
}

// ---------------------------------------------------------------------------
// GEMM + in-epilogue candidate collection (no m2 store). B frags paired:
// per k-step a warp issues 2 LDS.128 (A) + 4 LDS.128 (B) for 16 HMMAs.
// ---------------------------------------------------------------------------
extern __shared__ char smem_raw[];

__global__ void __launch_bounds__(THREADS, 2)
vq_gemm(void) {
    const int tid  = threadIdx.x;
    const int lane = tid & 31;
    const int wid  = tid >> 5;
    const int wm   = wid >> 1;
    const int wn   = wid & 1;
    const int gid  = lane >> 2;
    const int tig  = lane & 3;
    const int t0   = blockIdx.x * BM;
    const int owner = wn * 4 + tig;

    char* sA = smem_raw;
    char* sB[2] = { smem_raw + SA_BYTES, smem_raw + SA_BYTES + SB_BYTES };
    uint32_t sAu = smem_u32(sA);
    uint32_t sBu[2] = { smem_u32(sB[0]), smem_u32(sB[1]) };

    // load A (64 KB) once
    {
        const uint4* gA = g_za + (size_t)blockIdx.x * 8 * 512;
#pragma unroll
        for (int j = 0; j < 16; j++) {
            int f = tid + j * THREADS;
            cp_async16(sAu + f * 16, gA + f);
        }
    }
    auto fillB = [&](int buf, int it) {
        int chunk = it >> 2, s = it & 3;
#pragma unroll
        for (int j = 0; j < 4; j++) {
            int f = tid + j * THREADS;      // 0..1023 = ksl*256 + hp*32 + lane
            int l2 = f & 31, hp = (f >> 5) & 7, ksl = f >> 8;
            const uint4* src = g_eb4 + (size_t)(chunk * 8 + hp) * 512
                               + (s * STG_KS + ksl) * 32 + l2;
            cp_async16(sBu[buf] + f * 16, src);
        }
    };
    fillB(0, 0); cp_commit();
    fillB(1, 1); cp_commit();

    // per-owned-row filter state (4 rows: idx = im*2+h)
    float rmax4[4] = {-3.0e38f, -3.0e38f, -3.0e38f, -3.0e38f};
    float thr4[4]  = {-3.0e38f, -3.0e38f, -3.0e38f, -3.0e38f};
    float M4[4];
    int   cnt4[4]  = {0, 0, 0, 0};
    size_t base4[4];
#pragma unroll
    for (int im = 0; im < 2; im++)
#pragma unroll
        for (int h = 0; h < 2; h++) {
            int trow = t0 + (wm * 2 + im) * 16 + h * 8 + gid;
            M4[im * 2 + h] = margin_of(g_z2[trow], g_az[trow]);
            base4[im * 2 + h] = ((size_t)trow * 8 + owner) * NC;
        }

    float acc[2][8][4];

    for (int it = 0; it < NIT; it++) {
        const int chunk = it >> 2, s = it & 3, buf = it & 1;
        if (it + 1 < NIT) cp_wait1(); else cp_wait0();
        __syncthreads();

        if (s == 0) {
#pragma unroll
            for (int im = 0; im < 2; im++)
#pragma unroll
                for (int in = 0; in < 8; in++)
#pragma unroll
                    for (int q = 0; q < 4; q++) acc[im][in][q] = 0.f;
        }

        const char* pB = sB[buf];
#pragma unroll
        for (int ksl = 0; ksl < STG_KS; ksl++) {
            int ks = s * STG_KS + ksl;
            uint4 a[2];
#pragma unroll
            for (int im = 0; im < 2; im++) {
                int mg = wm * 2 + im;
                a[im] = *(const uint4*)(sA + (((mg * 16 + ks) * 32 + lane) << 4));
            }
#pragma unroll
            for (int ip = 0; ip < 4; ip++) {
                uint4 b2 = *(const uint4*)(pB + (((ksl * 8 + wn * 4 + ip) * 32 + lane) << 4));
#pragma unroll
                for (int im = 0; im < 2; im++) {
                    mma_f16(acc[im][2 * ip],     a[im], b2.x, b2.y);
                    mma_f16(acc[im][2 * ip + 1], a[im], b2.z, b2.w);
                }
            }
        }
        __syncthreads();
        if (it + 2 < NIT) { fillB(buf, it + 2); cp_commit(); }

        if (s == 3) {
            // epilogue: candidate filter
            const int ecbase = chunk * 128 + wn * 64 + 2 * tig;
#pragma unroll
            for (int im = 0; im < 2; im++)
#pragma unroll
                for (int h = 0; h < 2; h++) {
                    const int r = im * 2 + h;
#pragma unroll
                    for (int in = 0; in < 8; in++) {
                        float m0 = acc[im][in][h * 2 + 0] * DESCALE;
                        float m1 = acc[im][in][h * 2 + 1] * DESCALE;
                        int e0 = ecbase + in * 8;
                        if (m0 >= thr4[r]) {
                            if (cnt4[r] < NC)
                                g_cand[base4[r] + cnt4[r]] =
                                    make_int2(__float_as_int(m0), e0);
                            cnt4[r]++;
                            if (m0 > rmax4[r]) { rmax4[r] = m0; thr4[r] = m0 - M4[r]; }
                        }
                        if (m1 >= thr4[r]) {
                            if (cnt4[r] < NC)
                                g_cand[base4[r] + cnt4[r]] =
                                    make_int2(__float_as_int(m1), e0 + 1);
                            cnt4[r]++;
                            if (m1 > rmax4[r]) { rmax4[r] = m1; thr4[r] = m1 - M4[r]; }
                        }
                    }
                }
        }
    }

    // publish per-owner state
#pragma unroll
    for (int im = 0; im < 2; im++)
#pragma unroll
        for (int h = 0; h < 2; h++) {
            const int r = im * 2 + h;
            int trow = t0 + (wm * 2 + im) * 16 + h * 8 + gid;
            g_ccnt[trow * 8 + owner] = cnt4[r];
            g_rmax[trow * 8 + owner] = rmax4[r];
        }
}

// ---------------------------------------------------------------------------
// Pick + gather + loss: warp per token. Reads only the tiny candidate lists.
// ---------------------------------------------------------------------------
#define PCAP (8 * NC)
__global__ void __launch_bounds__(256, 1)
vq_pick(const float* __restrict__ z, const float* __restrict__ emb,
        float* __restrict__ out_zq, float* __restrict__ out_idx_f) {
    __shared__ float sz[8][D];
    __shared__ int   slist[8][PCAP];
    __shared__ int   scnt[8];
    __shared__ float sws[8];
    const int w    = threadIdx.x >> 5;
    const int lane = threadIdx.x & 31;
    const int t    = blockIdx.x * 8 + w;

    {
        float4* dst = (float4*)sz[w];
        const float4* src = (const float4*)(z + (size_t)t * D);
        dst[lane] = src[lane];
        dst[lane + 32] = src[lane + 32];
    }
    if (lane == 0) scnt[w] = 0;
    __syncwarp();

    // global max + overflow check over the 8 owners
    float r = (lane < 8) ? g_rmax[t * 8 + lane] : -3.0e38f;
    int   c = (lane < 8) ? g_ccnt[t * 8 + lane] : 0;
#pragma unroll
    for (int o = 16; o; o >>= 1) r = fmaxf(r, __shfl_xor_sync(0xffffffffu, r, o));
    bool ovf = __any_sync(0xffffffffu, c > NC);

    const float z2 = g_z2[t];
    const float thr = r - margin_of(z2, g_az[t]);

    if (!ovf && lane < 8) {
        const int2* src = g_cand + ((size_t)t * 8 + lane) * NC;
        for (int i = 0; i < c; i++) {
            int2 cd = src[i];
            if (__int_as_float(cd.x) >= thr) {
                int pos = atomicAdd(&scnt[w], 1);
                slist[w][pos] = cd.y;
            }
        }
    }
    __syncwarp();
    int cnt = scnt[w];

    float bv = 3.0e38f;
    int   bi = 0x7fffffff;
    const float* zz = sz[w];

    if (!ovf) {
        for (int base = 0; base < cnt; base += 32) {
            int ci = base + lane;
            float dv = 3.0e38f;
            int   e  = 0x7fffffff;
            if (ci < cnt) {
                e = slist[w][ci];
                const float* er = emb + (size_t)e * D;
                float d = 0.f;
#pragma unroll 8
                for (int k = 0; k < D; k++) d = fmaf(zz[k], er[k], d);
                dv = __fadd_rn(z2, -__fmul_rn(2.f, d));
            }
            if (dv < bv || (dv == bv && e < bi)) { bv = dv; bi = e; }
        }
    } else {
        // overflow fallback: exact full scan (codes ascending per lane)
        for (int cc = 0; cc < 256; cc++) {
            int e = lane * 256 + cc;
            const float* er = emb + (size_t)e * D;
            float d = 0.f;
#pragma unroll 8
            for (int k = 0; k < D; k++) d = fmaf(zz[k], er[k], d);
            float dv = __fadd_rn(z2, -__fmul_rn(2.f, d));
            if (dv < bv) { bv = dv; bi = e; }
        }
    }
#pragma unroll
    for (int o = 16; o; o >>= 1) {
        float ov = __shfl_xor_sync(0xffffffffu, bv, o);
        int   oi = __shfl_xor_sync(0xffffffffu, bi, o);
        if (ov < bv || (ov == bv && oi < bi)) { bv = ov; bi = oi; }
    }
    bi = __shfl_sync(0xffffffffu, bi, 0);
    if (lane == 0) out_idx_f[t] = (float)bi;

    // gather + STE-exact output + loss partial
    float lsum = 0.f;
    {
        const float* er = emb + (size_t)bi * D;
        float* o = out_zq + (size_t)t * D;
#pragma unroll
        for (int i = 0; i < D / 32; i++) {
            int cc = lane + 32 * i;
            float q  = er[cc];
            float zc = zz[cc];
            float d  = __fadd_rn(q, -zc);
            lsum = fmaf(d, d, lsum);
            o[cc] = __fadd_rn(zc, d);
        }
    }
#pragma unroll
    for (int o = 16; o; o >>= 1) lsum += __shfl_xor_sync(0xffffffffu, lsum, o);
    if (lane == 0) sws[w] = lsum;
    __syncthreads();
    if (threadIdx.x == 0) {
        float tsum = 0.f;
#pragma unroll
        for (int i = 0; i < 8; i++) tsum += sws[i];
        g_partial[blockIdx.x] = tsum;
    }
}

// ---------------------------------------------------------------------------
__global__ void vq_finalize_kernel(float* __restrict__ out_loss) {
    int tid = threadIdx.x;             // 256 threads, 4096 partials
    double s = 0.0;
#pragma unroll
    for (int i = 0; i < 16; i++) s += (double)g_partial[tid + 256 * i];
#pragma unroll
    for (int o = 16; o; o >>= 1) s += __shfl_xor_sync(0xffffffffu, s, o);
    __shared__ double ws[8];
    if ((tid & 31) == 0) ws[tid >> 5] = s;
    __syncthreads();
    if (tid == 0) {
        double t = 0.0;
#pragma unroll
        for (int i = 0; i < 8; i++) t += ws[i];
        *out_loss = (float)((1.0 + (double)BETA) * t / (double)((size_t)T_TOTAL * D));
    }
}

// ---------------------------------------------------------------------------
extern "C" void kernel_launch(void* const* d_in, const int* in_sizes, int n_in,
                              void* d_out, int out_size) {
    const float* z   = (const float*)d_in[0];   // [8,4096,256] fp32
    const float* emb = (const float*)d_in[1];   // [8192,256] fp32
    float* out       = (float*)d_out;
    float* out_zq    = out;
    float* out_loss  = out + (size_t)T_TOTAL * D;
    float* out_idx   = out + (size_t)T_TOTAL * D + 1;

    vq_prep_z<<<2048, THREADS>>>(z);
    vq_prep_e<<<512, THREADS>>>(emb);
    vq_norms<<<T_TOTAL / 8, 256>>>(z);

    size_t smem_bytes = SA_BYTES + 2 * SB_BYTES;   // 98304
    cudaFuncSetAttribute(vq_gemm,
                         cudaFuncAttributeMaxDynamicSharedMemorySize,
                         (int)smem_bytes);
    vq_gemm<<<T_TOTAL / BM, THREADS, smem_bytes>>>();

    vq_pick<<<T_TOTAL / 8, 256>>>(z, emb, out_zq, out_idx);
    vq_finalize_kernel<<<1, 256>>>(out_loss);
}